// round 7
// baseline (speedup 1.0000x reference)
#include <cuda_runtime.h>
#include <cuda_bf16.h>
#include <stdint.h>
#include <math.h>

// ---------------------------------------------------------------------------
// EMLLA block, bf16 mma.sync GEMMs with cp.async.bulk (UBLKCP) tile staging.
// Both GEMM operands are contiguous gmem spans -> 2 bulk copies per CTA
// instead of ~4600 LDGSTS (whose 8cyc/op issue cost dominated rounds 4-6).
// B=16, H=W=56, C=192, 6 heads x 32.
// ---------------------------------------------------------------------------

constexpr int Himg = 56, Wimg = 56, Lseq = 3136, Cdim = 192;
constexpr int NHEAD = 6, HDIM = 32, BATCH = 16;
constexpr int BL = BATCH * Lseq;              // 50176 rows
constexpr float LN_EPS = 1e-5f;

// Scratch (device globals: allocation-free, graph-capture safe)
__device__ __align__(16) __nv_bfloat16 g_xnb [(size_t)BL * Cdim];
__device__ __align__(16) __nv_bfloat16 g_h0b [(size_t)BL * Cdim];
__device__ __align__(16) __nv_bfloat16 g_actb[(size_t)BL * Cdim];
__device__ __align__(16) __nv_bfloat16 g_hb  [(size_t)BL * Cdim];
__device__ __align__(16) __nv_bfloat16 g_qkb [(size_t)BL * 2 * Cdim];
__device__ __align__(16) __nv_bfloat16 g_gb  [(size_t)BL * Cdim];
__device__ __align__(16) float g_att[(size_t)BL * Cdim];
__device__ __align__(16) float g_kv [BATCH * NHEAD * HDIM * HDIM];
__device__ __align__(16) float g_km [BATCH * NHEAD * HDIM];
// bf16 weights, TRANSPOSED to [N, K] K-major (contiguous per-N-block spans;
// consumed by non-trans ldmatrix as col-major KxN)
__device__ __align__(16) __nv_bfloat16 g_wcat[2 * Cdim * Cdim];   // [384,192]
__device__ __align__(16) __nv_bfloat16 g_qkw [2 * Cdim * Cdim];   // [384,192]
__device__ __align__(16) __nv_bfloat16 g_outw[Cdim * Cdim];       // [192,192]

// ---------------------------------------------------------------------------
// helpers
// ---------------------------------------------------------------------------
__device__ __forceinline__ uint32_t smem_u32(const void* p) {
    return (uint32_t)__cvta_generic_to_shared(p);
}
__device__ __forceinline__ void ldm_x4(uint32_t& r0, uint32_t& r1, uint32_t& r2,
                                       uint32_t& r3, uint32_t a) {
    asm volatile("ldmatrix.sync.aligned.m8n8.x4.shared.b16 {%0,%1,%2,%3}, [%4];"
                 : "=r"(r0), "=r"(r1), "=r"(r2), "=r"(r3) : "r"(a));
}
__device__ __forceinline__ void mma16816(float* c, uint32_t a0, uint32_t a1,
                                         uint32_t a2, uint32_t a3,
                                         uint32_t b0, uint32_t b1) {
    asm volatile(
        "mma.sync.aligned.m16n8k16.row.col.f32.bf16.bf16.f32 "
        "{%0,%1,%2,%3}, {%4,%5,%6,%7}, {%8,%9}, {%0,%1,%2,%3};"
        : "+f"(c[0]), "+f"(c[1]), "+f"(c[2]), "+f"(c[3])
        : "r"(a0), "r"(a1), "r"(a2), "r"(a3), "r"(b0), "r"(b1));
}
__device__ __forceinline__ void bulk_g2s(uint32_t dst, const void* src,
                                         uint32_t bytes, uint32_t mbar) {
    asm volatile(
        "cp.async.bulk.shared::cta.global.mbarrier::complete_tx::bytes "
        "[%0], [%1], %2, [%3];"
        :: "r"(dst), "l"(src), "r"(bytes), "r"(mbar) : "memory");
}
__device__ __forceinline__ __nv_bfloat162 pack2(float a, float b) {
    return __floats2bfloat162_rn(a, b);
}

#define MBARRIER_INIT(mbar, count) \
    asm volatile("mbarrier.init.shared.b64 [%0], %1;" \
        :: "r"((uint32_t)(mbar)), "r"((uint32_t)(count)) : "memory")
#define MBARRIER_EXPECT_TX(mbar, bytes) \
    asm volatile("mbarrier.arrive.expect_tx.shared.b64 _, [%0], %1;" \
        :: "r"((uint32_t)(mbar)), "r"((uint32_t)(bytes)) : "memory")
#define MBARRIER_WAIT_PARITY(mbar, parity) do { \
    uint32_t _m = (uint32_t)(mbar); uint32_t _p = (uint32_t)(parity); uint32_t _d; \
    asm volatile( \
        "{\n\t.reg .pred p;\n\t" \
        "mbarrier.try_wait.parity.acquire.cta.shared::cta.b64 p, [%1], %2;\n\t" \
        "selp.b32 %0, 1, 0, p;\n\t}" \
        : "=r"(_d) : "r"(_m), "r"(_p) : "memory"); \
    if (!_d) { \
        asm volatile( \
            "{\n\t.reg .pred P1;\n\t" \
            "WAIT_LOOP_%=:\n\t" \
            "mbarrier.try_wait.parity.acquire.cta.shared::cta.b64 P1, [%0], %1, 0x989680;\n\t" \
            "@P1 bra.uni WAIT_DONE_%=;\n\t" \
            "bra.uni WAIT_LOOP_%=;\n\t" \
            "WAIT_DONE_%=:\n\t}" \
            :: "r"(_m), "r"(_p) : "memory"); \
    } \
} while (0)

// ---------------------------------------------------------------------------
// weight convert + transpose: W[K,N] fp32 -> Wt[N,K] bf16
// ---------------------------------------------------------------------------
__global__ void convw_kernel(const float* __restrict__ in_w, const float* __restrict__ act_w,
                             const float* __restrict__ qk_w, const float* __restrict__ out_w)
{
    int i = blockIdx.x * 256 + threadIdx.x;
    if (i < 2 * Cdim * Cdim) {
        int n = i / Cdim, k = i % Cdim;
        float v = (n < Cdim) ? in_w[k * Cdim + n] : act_w[k * Cdim + (n - Cdim)];
        g_wcat[i] = __float2bfloat16(v);
        g_qkw[i]  = __float2bfloat16(qk_w[k * 2 * Cdim + n]);
    }
    if (i < Cdim * Cdim) {
        int n = i / Cdim, k = i % Cdim;
        g_outw[i] = __float2bfloat16(out_w[k * Cdim + n]);
    }
}

// ---------------------------------------------------------------------------
// LayerNorm -> bf16: one warp per row of 192
// ---------------------------------------------------------------------------
__global__ void ln_kernel(const float* __restrict__ x, const float* __restrict__ gamma,
                          const float* __restrict__ beta, __nv_bfloat16* __restrict__ out) {
    int row  = blockIdx.x * 8 + (threadIdx.x >> 5);
    int lane = threadIdx.x & 31;
    const float* xr = x + (size_t)row * Cdim;
    float v[6]; float s = 0.f, ss = 0.f;
#pragma unroll
    for (int i = 0; i < 6; i++) { v[i] = xr[lane + 32 * i]; s += v[i]; ss += v[i] * v[i]; }
#pragma unroll
    for (int o = 16; o > 0; o >>= 1) {
        s  += __shfl_xor_sync(0xffffffffu, s,  o);
        ss += __shfl_xor_sync(0xffffffffu, ss, o);
    }
    float mu   = s * (1.f / Cdim);
    float var  = ss * (1.f / Cdim) - mu * mu;
    float rstd = rsqrtf(var + LN_EPS);
    __nv_bfloat16* orow = out + (size_t)row * Cdim;
#pragma unroll
    for (int i = 0; i < 6; i++) {
        int c = lane + 32 * i;
        orow[c] = __float2bfloat16((v[i] - mu) * rstd * gamma[c] + beta[c]);
    }
}

// ---------------------------------------------------------------------------
// bulk-staged bf16 GEMM: CTA tile 128 x BN, K = 192 fixed.
// A [M,192] row-block: ONE contiguous 48KB bulk copy.
// Wt [N,192] n-block:  ONE contiguous BN*384B bulk copy.
// 8 warps (4x2), warp tile 32 x BN/2, m16n8k16, no inner barriers.
// MODE 0: split at col 192 (Y1 none | Y2 silu), out stride Cdim
// MODE 1: elu+1 -> Y1 (stride N);  MODE 2: +bias +fp32 resid -> Yf (stride N)
// ---------------------------------------------------------------------------
constexpr int GK = 192;
constexpr int SM_A = 1024;                       // mbar at 0
template <int BN, int MODE>
__global__ __launch_bounds__(256, 2) void gemm_blk(
    const __nv_bfloat16* __restrict__ A, const __nv_bfloat16* __restrict__ Wt,
    const float* __restrict__ bias1, const float* __restrict__ bias2,
    const float* __restrict__ resid,
    __nv_bfloat16* __restrict__ Y1, __nv_bfloat16* __restrict__ Y2,
    float* __restrict__ Yf, int M, int N)
{
    constexpr int ABYTES = 128 * GK * 2;         // 49152
    constexpr int BBYTES = BN * GK * 2;
    constexpr int NT = BN / 16;                  // n8-tiles per warp
    constexpr int NP = BN / 32;                  // ldm_x4 per k-step for B

    extern __shared__ __align__(16) char smem[];
    uint32_t sb = smem_u32(smem);
    uint32_t as_base = sb + SM_A;
    uint32_t bs_base = as_base + ABYTES;

    int tid  = threadIdx.x;
    int bm   = blockIdx.y * 128, bn = blockIdx.x * BN;
    int warp = tid >> 5, lane = tid & 31;
    int wm   = (warp & 3) * 32, wn = (warp >> 2) * (BN / 2);

    if (tid == 0) MBARRIER_INIT(sb, 1);
    __syncthreads();
    if (tid == 0) {
        MBARRIER_EXPECT_TX(sb, ABYTES + BBYTES);
        bulk_g2s(as_base, A  + (size_t)bm * GK, ABYTES, sb);
        bulk_g2s(bs_base, Wt + (size_t)bn * GK, BBYTES, sb);
    }

    float acc[2][NT][4];
#pragma unroll
    for (int i = 0; i < 2; i++)
#pragma unroll
        for (int j = 0; j < NT; j++)
#pragma unroll
            for (int l = 0; l < 4; l++) acc[i][j][l] = 0.f;

    // A frag addresses (row-major MxK, non-trans ldmatrix)
    int a_row = wm + (lane & 7) + ((lane >> 3) & 1) * 8;
    int a_col = (lane >> 4) * 8;
    // B frag addresses ([N,K] = col-major KxN, non-trans ldmatrix):
    // lanes 0-7: n 0-7 / k 0-7 ; 8-15: n 0-7 / k 8-15 ;
    // 16-23: n 8-15 / k 0-7 ; 24-31: n 8-15 / k 8-15
    int b_n = wn + (lane & 7) + ((lane >> 4) & 1) * 8;
    int b_k = ((lane >> 3) & 1) * 8;

    MBARRIER_WAIT_PARITY(sb, 0);

    // ---- 12 unrolled k-steps, no barriers ----
#pragma unroll
    for (int s = 0; s < 12; s++) {
        uint32_t afr[2][4];
#pragma unroll
        for (int mt = 0; mt < 2; mt++) {
            uint32_t addr = as_base + ((a_row + mt * 16) * GK + a_col + s * 16) * 2;
            ldm_x4(afr[mt][0], afr[mt][1], afr[mt][2], afr[mt][3], addr);
        }
        uint32_t bfr[NT][2];
#pragma unroll
        for (int p = 0; p < NP; p++) {
            uint32_t addr = bs_base + ((b_n + p * 16) * GK + b_k + s * 16) * 2;
            uint32_t r0, r1, r2, r3;
            ldm_x4(r0, r1, r2, r3, addr);
            bfr[p * 2 + 0][0] = r0; bfr[p * 2 + 0][1] = r1;
            bfr[p * 2 + 1][0] = r2; bfr[p * 2 + 1][1] = r3;
        }
#pragma unroll
        for (int mt = 0; mt < 2; mt++)
#pragma unroll
            for (int nt = 0; nt < NT; nt++)
                mma16816(acc[mt][nt], afr[mt][0], afr[mt][1], afr[mt][2],
                         afr[mt][3], bfr[nt][0], bfr[nt][1]);
    }

    // ---- epilogue ----
    int r0 = lane >> 2, c0 = (lane & 3) * 2;
#pragma unroll
    for (int mt = 0; mt < 2; mt++) {
#pragma unroll
        for (int half = 0; half < 2; half++) {
            int row = bm + wm + mt * 16 + r0 + half * 8;
#pragma unroll
            for (int nt = 0; nt < NT; nt++) {
                int col = bn + wn + nt * 8 + c0;
                float v0 = acc[mt][nt][half * 2 + 0];
                float v1 = acc[mt][nt][half * 2 + 1];
                if (MODE == 0) {
                    bool first = (col < Cdim);    // pairs never straddle 192
                    int cl = first ? col : col - Cdim;
                    const float* bs = first ? bias1 : bias2;
                    v0 += bs[cl]; v1 += bs[cl + 1];
                    if (!first) {
                        v0 = v0 / (1.f + expf(-v0));
                        v1 = v1 / (1.f + expf(-v1));
                    }
                    __nv_bfloat16* dst = first ? Y1 : Y2;
                    *(__nv_bfloat162*)&dst[(size_t)row * Cdim + cl] = pack2(v0, v1);
                } else if (MODE == 1) {
                    v0 += bias1[col]; v1 += bias1[col + 1];
                    v0 = (v0 > 0.f) ? v0 + 1.f : expf(v0);
                    v1 = (v1 > 0.f) ? v1 + 1.f : expf(v1);
                    *(__nv_bfloat162*)&Y1[(size_t)row * N + col] = pack2(v0, v1);
                } else {
                    v0 += bias1[col]; v1 += bias1[col + 1];
                    float2 rr = *(const float2*)&resid[(size_t)row * N + col];
                    v0 += rr.x; v1 += rr.y;
                    float2 o; o.x = v0; o.y = v1;
                    *(float2*)&Yf[(size_t)row * N + col] = o;
                }
            }
        }
    }
}

// ---------------------------------------------------------------------------
// Depthwise 3x3 SAME conv + silu, bf16x2: 96 threads (2ch each), 4 rows/thread
// ---------------------------------------------------------------------------
__global__ void dwconv_silu_kernel(const __nv_bfloat162* __restrict__ in,
                                   const float* __restrict__ w,
                                   const float* __restrict__ bias,
                                   __nv_bfloat162* __restrict__ out)
{
    int blk = blockIdx.x;
    int c2  = threadIdx.x;              // 0..95
    int x   = blk % Wimg;
    int t   = blk / Wimg;
    int y4  = t % (Himg / 4);
    int b   = t / (Himg / 4);
    int y0  = y4 * 4;

    float2 wv[9];
#pragma unroll
    for (int i = 0; i < 9; i++) wv[i] = *(const float2*)&w[i * Cdim + 2 * c2];
    float2 bb = *(const float2*)&bias[2 * c2];
    float2 acc[4];
#pragma unroll
    for (int i = 0; i < 4; i++) acc[i] = bb;

#pragma unroll
    for (int dx = 0; dx < 3; dx++) {
        int xx = x + dx - 1;
        if (xx < 0 || xx >= Wimg) continue;
#pragma unroll
        for (int ry = -1; ry < 5; ry++) {
            int yy = y0 + ry;
            if (yy < 0 || yy >= Himg) continue;
            float2 v = __bfloat1622float2(in[((size_t)(b * Himg + yy) * Wimg + xx) * 96 + c2]);
#pragma unroll
            for (int oy = 0; oy < 4; oy++) {
                int dy = ry - oy + 1;
                if (dy >= 0 && dy < 3) {
                    acc[oy].x = fmaf(v.x, wv[dy * 3 + dx].x, acc[oy].x);
                    acc[oy].y = fmaf(v.y, wv[dy * 3 + dx].y, acc[oy].y);
                }
            }
        }
    }
#pragma unroll
    for (int oy = 0; oy < 4; oy++) {
        float a0 = acc[oy].x, a1 = acc[oy].y;
        a0 = a0 / (1.f + expf(-a0));
        a1 = a1 / (1.f + expf(-a1));
        out[((size_t)(b * Himg + y0 + oy) * Wimg + x) * 96 + c2] = pack2(a0, a1);
    }
}

// Fused: g = (att + dwconv(h)+lepe_b) * act_res
__global__ void lepe_mul_kernel(const __nv_bfloat162* __restrict__ hin,
                                const float* __restrict__ w,
                                const float* __restrict__ bias,
                                const float* __restrict__ att,
                                const __nv_bfloat162* __restrict__ actres,
                                __nv_bfloat162* __restrict__ out)
{
    int blk = blockIdx.x;
    int c2  = threadIdx.x;
    int x   = blk % Wimg;
    int t   = blk / Wimg;
    int y4  = t % (Himg / 4);
    int b   = t / (Himg / 4);
    int y0  = y4 * 4;

    float2 wv[9];
#pragma unroll
    for (int i = 0; i < 9; i++) wv[i] = *(const float2*)&w[i * Cdim + 2 * c2];
    float2 bb = *(const float2*)&bias[2 * c2];
    float2 acc[4];
#pragma unroll
    for (int i = 0; i < 4; i++) acc[i] = bb;

#pragma unroll
    for (int dx = 0; dx < 3; dx++) {
        int xx = x + dx - 1;
        if (xx < 0 || xx >= Wimg) continue;
#pragma unroll
        for (int ry = -1; ry < 5; ry++) {
            int yy = y0 + ry;
            if (yy < 0 || yy >= Himg) continue;
            float2 v = __bfloat1622float2(hin[((size_t)(b * Himg + yy) * Wimg + xx) * 96 + c2]);
#pragma unroll
            for (int oy = 0; oy < 4; oy++) {
                int dy = ry - oy + 1;
                if (dy >= 0 && dy < 3) {
                    acc[oy].x = fmaf(v.x, wv[dy * 3 + dx].x, acc[oy].x);
                    acc[oy].y = fmaf(v.y, wv[dy * 3 + dx].y, acc[oy].y);
                }
            }
        }
    }
#pragma unroll
    for (int oy = 0; oy < 4; oy++) {
        size_t pix = (size_t)(b * Himg + y0 + oy) * Wimg + x;
        float2 at = *(const float2*)&att[pix * Cdim + 2 * c2];
        float2 ar = __bfloat1622float2(actres[pix * 96 + c2]);
        out[pix * 96 + c2] = pack2((at.x + acc[oy].x) * ar.x,
                                   (at.y + acc[oy].y) * ar.y);
    }
}

// ---------------------------------------------------------------------------
// kv[b,h] = k^T v / L  (32x32), kmean = mean_n k
// ---------------------------------------------------------------------------
__global__ void kv_kernel(const __nv_bfloat16* __restrict__ qk,
                          const __nv_bfloat16* __restrict__ hv,
                          float* __restrict__ kv, float* __restrict__ km)
{
    int bh = blockIdx.x;
    int b = bh / NHEAD, hd = bh % NHEAD;
    __shared__ float skv[HDIM * HDIM];
    __shared__ float skm[HDIM];
    int tid = threadIdx.x;
    for (int i = tid; i < HDIM * HDIM; i += blockDim.x) skv[i] = 0.f;
    if (tid < HDIM) skm[tid] = 0.f;
    __syncthreads();

    int lane = tid & 31, warp = tid >> 5;
    float acc[HDIM];
#pragma unroll
    for (int e = 0; e < HDIM; e++) acc[e] = 0.f;
    float acck = 0.f;

    for (int n = warp; n < Lseq; n += 8) {
        size_t rowq = (size_t)(b * Lseq + n) * (2 * Cdim);
        float kd = __bfloat162float(qk[rowq + Cdim + hd * HDIM + lane]);
        float ve = __bfloat162float(hv[(size_t)(b * Lseq + n) * Cdim + hd * HDIM + lane]);
        acck += kd;
#pragma unroll
        for (int e = 0; e < HDIM; e++)
            acc[e] = fmaf(kd, __shfl_sync(0xffffffffu, ve, e), acc[e]);
    }
#pragma unroll
    for (int e = 0; e < HDIM; e++) atomicAdd(&skv[lane * HDIM + e], acc[e]);
    atomicAdd(&skm[lane], acck);
    __syncthreads();

    const float invL = 1.f / (float)Lseq;
    for (int i = tid; i < HDIM * HDIM; i += blockDim.x)
        kv[(size_t)bh * HDIM * HDIM + i] = skv[i] * invL;
    if (tid < HDIM) km[bh * HDIM + tid] = skm[tid] * invL;
}

// ---------------------------------------------------------------------------
// att[n, h*32+e] = z * sum_d q[n,d]*kv[d,e];  z = 1/(q.kmean + 1e-6)
// ---------------------------------------------------------------------------
__global__ void att_kernel(const __nv_bfloat16* __restrict__ qk,
                           const float* __restrict__ kv,
                           const float* __restrict__ km, float* __restrict__ att)
{
    int bh = blockIdx.x;
    int b = bh / NHEAD, hd = bh % NHEAD;
    __shared__ float skv[HDIM * HDIM];
    __shared__ float skm[HDIM];
    int tid = threadIdx.x;
    for (int i = tid; i < HDIM * HDIM; i += blockDim.x)
        skv[i] = kv[(size_t)bh * HDIM * HDIM + i];
    if (tid < HDIM) skm[tid] = km[bh * HDIM + tid];
    __syncthreads();

    int lane = tid & 31, warp = tid >> 5;
    const int per = Lseq / 8;
    int n0 = blockIdx.y * per;
    for (int n = n0 + warp; n < n0 + per; n += 8) {
        float qe = __bfloat162float(qk[(size_t)(b * Lseq + n) * (2 * Cdim) + hd * HDIM + lane]);
        float p = qe * skm[lane];
#pragma unroll
        for (int o = 16; o > 0; o >>= 1) p += __shfl_xor_sync(0xffffffffu, p, o);
        float z = 1.f / (p + 1e-6f);
        float a = 0.f;
#pragma unroll
        for (int d = 0; d < HDIM; d++)
            a = fmaf(__shfl_sync(0xffffffffu, qe, d), skv[d * HDIM + lane], a);
        att[(size_t)(b * Lseq + n) * Cdim + hd * HDIM + lane] = a * z;
    }
}

// ---------------------------------------------------------------------------
extern "C" void kernel_launch(void* const* d_in, const int* in_sizes, int n_in,
                              void* d_out, int out_size)
{
    const float* x      = (const float*)d_in[0];
    const float* norm_g = (const float*)d_in[1];
    const float* norm_b = (const float*)d_in[2];
    const float* in_w   = (const float*)d_in[3];
    const float* in_b   = (const float*)d_in[4];
    const float* act_w  = (const float*)d_in[5];
    const float* act_b  = (const float*)d_in[6];
    const float* dwc_w  = (const float*)d_in[7];
    const float* dwc_b  = (const float*)d_in[8];
    const float* qk_w   = (const float*)d_in[9];
    const float* qk_b   = (const float*)d_in[10];
    const float* lepe_w = (const float*)d_in[11];
    const float* lepe_b = (const float*)d_in[12];
    const float* out_w  = (const float*)d_in[13];
    const float* out_b  = (const float*)d_in[14];
    float* out = (float*)d_out;

    __nv_bfloat16 *xnb, *h0b, *actb, *hb, *qkb, *gb, *wcat, *qkw, *outw;
    float *att, *kv, *km;
    cudaGetSymbolAddress((void**)&xnb,  g_xnb);
    cudaGetSymbolAddress((void**)&h0b,  g_h0b);
    cudaGetSymbolAddress((void**)&actb, g_actb);
    cudaGetSymbolAddress((void**)&hb,   g_hb);
    cudaGetSymbolAddress((void**)&qkb,  g_qkb);
    cudaGetSymbolAddress((void**)&gb,   g_gb);
    cudaGetSymbolAddress((void**)&att,  g_att);
    cudaGetSymbolAddress((void**)&kv,   g_kv);
    cudaGetSymbolAddress((void**)&km,   g_km);
    cudaGetSymbolAddress((void**)&wcat, g_wcat);
    cudaGetSymbolAddress((void**)&qkw,  g_qkw);
    cudaGetSymbolAddress((void**)&outw, g_outw);

    constexpr int SMEM128 = SM_A + 128 * GK * 2 + 128 * GK * 2;  // 99328
    constexpr int SMEM64  = SM_A + 128 * GK * 2 + 64  * GK * 2;  // 74752
    cudaFuncSetAttribute(gemm_blk<128, 0>, cudaFuncAttributeMaxDynamicSharedMemorySize, SMEM128);
    cudaFuncSetAttribute(gemm_blk<128, 1>, cudaFuncAttributeMaxDynamicSharedMemorySize, SMEM128);
    cudaFuncSetAttribute(gemm_blk<64,  2>, cudaFuncAttributeMaxDynamicSharedMemorySize, SMEM64);

    // 0) weights -> bf16 [N,K]
    convw_kernel<<<(2 * Cdim * Cdim + 255) / 256, 256>>>(in_w, act_w, qk_w, out_w);

    // 1) LayerNorm -> bf16
    ln_kernel<<<BL / 8, 256>>>(x, norm_g, norm_b, xnb);

    // 2) fused in-proj + act-proj (N=384, split epilogue)
    gemm_blk<128, 0><<<dim3(3, BL / 128), 256, SMEM128>>>(
        xnb, wcat, in_b, act_b, nullptr, h0b, actb, nullptr, BL, 2 * Cdim);

    // 3) dwconv + silu -> h
    int dwgrid = BATCH * (Himg / 4) * Wimg;
    dwconv_silu_kernel<<<dwgrid, 96>>>((const __nv_bfloat162*)h0b, dwc_w, dwc_b,
                                       (__nv_bfloat162*)hb);

    // 4) qk-proj with elu+1
    gemm_blk<128, 1><<<dim3(3, BL / 128), 256, SMEM128>>>(
        hb, qkw, qk_b, nullptr, nullptr, qkb, nullptr, nullptr, BL, 2 * Cdim);

    // 5) linear attention
    kv_kernel<<<BATCH * NHEAD, 256>>>(qkb, hb, kv, km);
    att_kernel<<<dim3(BATCH * NHEAD, 8), 256>>>(qkb, kv, km, att);

    // 6) g = (att + lepe) * act_res -> gb
    lepe_mul_kernel<<<dwgrid, 96>>>((const __nv_bfloat162*)hb, lepe_w, lepe_b, att,
                                    (const __nv_bfloat162*)actb, (__nv_bfloat162*)gb);

    // 7) out-proj + bias + shortcut -> fp32 out
    gemm_blk<64, 2><<<dim3(3, BL / 128), 256, SMEM64>>>(
        gb, outw, out_b, nullptr, x, nullptr, nullptr, out, BL, Cdim);
}

// round 8
// speedup vs baseline: 1.3884x; 1.3884x over previous
#include <cuda_runtime.h>
#include <cuda_bf16.h>
#include <stdint.h>
#include <math.h>

// ---------------------------------------------------------------------------
// EMLLA block: round-4 pipelined bf16 HMMA GEMMs + fast-math activations
// (__expf/__fdividef replace libdevice expf/fdiv which dominated epilogues).
// B=16, H=W=56, C=192, 6 heads x 32.
// ---------------------------------------------------------------------------

constexpr int Himg = 56, Wimg = 56, Lseq = 3136, Cdim = 192;
constexpr int NHEAD = 6, HDIM = 32, BATCH = 16;
constexpr int BL = BATCH * Lseq;              // 50176 rows
constexpr float LN_EPS = 1e-5f;

// Scratch (device globals: allocation-free, graph-capture safe)
__device__ __align__(16) __nv_bfloat16 g_xnb [(size_t)BL * Cdim];
__device__ __align__(16) __nv_bfloat16 g_h0b [(size_t)BL * Cdim];
__device__ __align__(16) __nv_bfloat16 g_actb[(size_t)BL * Cdim];
__device__ __align__(16) __nv_bfloat16 g_hb  [(size_t)BL * Cdim];
__device__ __align__(16) __nv_bfloat16 g_qkb [(size_t)BL * 2 * Cdim];
__device__ __align__(16) __nv_bfloat16 g_gb  [(size_t)BL * Cdim];
__device__ __align__(16) float g_att[(size_t)BL * Cdim];
__device__ __align__(16) float g_kv [BATCH * NHEAD * HDIM * HDIM];
__device__ __align__(16) float g_km [BATCH * NHEAD * HDIM];
// bf16 weights, [K, N] layout (B consumed K-major by ldmatrix.trans)
__device__ __align__(16) __nv_bfloat16 g_wcat[Cdim * 2 * Cdim];   // in_w | act_w
__device__ __align__(16) __nv_bfloat16 g_qkw [Cdim * 2 * Cdim];
__device__ __align__(16) __nv_bfloat16 g_outw[Cdim * Cdim];

// ---------------------------------------------------------------------------
// helpers
// ---------------------------------------------------------------------------
__device__ __forceinline__ uint32_t smem_u32(const void* p) {
    return (uint32_t)__cvta_generic_to_shared(p);
}
__device__ __forceinline__ void ldm_x4(uint32_t& r0, uint32_t& r1, uint32_t& r2,
                                       uint32_t& r3, uint32_t a) {
    asm volatile("ldmatrix.sync.aligned.m8n8.x4.shared.b16 {%0,%1,%2,%3}, [%4];"
                 : "=r"(r0), "=r"(r1), "=r"(r2), "=r"(r3) : "r"(a));
}
__device__ __forceinline__ void ldm_x4t(uint32_t& r0, uint32_t& r1, uint32_t& r2,
                                        uint32_t& r3, uint32_t a) {
    asm volatile("ldmatrix.sync.aligned.m8n8.x4.trans.shared.b16 {%0,%1,%2,%3}, [%4];"
                 : "=r"(r0), "=r"(r1), "=r"(r2), "=r"(r3) : "r"(a));
}
__device__ __forceinline__ void mma16816(float* c, uint32_t a0, uint32_t a1,
                                         uint32_t a2, uint32_t a3,
                                         uint32_t b0, uint32_t b1) {
    asm volatile(
        "mma.sync.aligned.m16n8k16.row.col.f32.bf16.bf16.f32 "
        "{%0,%1,%2,%3}, {%4,%5,%6,%7}, {%8,%9}, {%0,%1,%2,%3};"
        : "+f"(c[0]), "+f"(c[1]), "+f"(c[2]), "+f"(c[3])
        : "r"(a0), "r"(a1), "r"(a2), "r"(a3), "r"(b0), "r"(b1));
}
__device__ __forceinline__ void cpa16(uint32_t dst, const void* src) {
    asm volatile("cp.async.cg.shared.global [%0], [%1], 16;" :: "r"(dst), "l"(src));
}
__device__ __forceinline__ __nv_bfloat162 pack2(float a, float b) {
    return __floats2bfloat162_rn(a, b);
}
// fast activations (MUFU-based)
__device__ __forceinline__ float fast_silu(float v) {
    return __fdividef(v, 1.f + __expf(-v));
}
__device__ __forceinline__ float fast_elu1(float v) {
    return (v > 0.f) ? v + 1.f : __expf(v);
}

// ---------------------------------------------------------------------------
// weight conversion: fp32 [K,N] -> bf16 [K,N] (+ concat in_w|act_w)
// ---------------------------------------------------------------------------
__global__ void convw_kernel(const float* __restrict__ in_w, const float* __restrict__ act_w,
                             const float* __restrict__ qk_w, const float* __restrict__ out_w)
{
    int i = blockIdx.x * 256 + threadIdx.x;
    if (i < Cdim * 2 * Cdim) {
        int r = i / (2 * Cdim), c = i % (2 * Cdim);
        float v = (c < Cdim) ? in_w[r * Cdim + c] : act_w[r * Cdim + (c - Cdim)];
        g_wcat[i] = __float2bfloat16(v);
        g_qkw[i]  = __float2bfloat16(qk_w[i]);
    }
    if (i < Cdim * Cdim) g_outw[i] = __float2bfloat16(out_w[i]);
}

// ---------------------------------------------------------------------------
// LayerNorm -> bf16: one warp per row of 192
// ---------------------------------------------------------------------------
__global__ void ln_kernel(const float* __restrict__ x, const float* __restrict__ gamma,
                          const float* __restrict__ beta, __nv_bfloat16* __restrict__ out) {
    int row  = blockIdx.x * 8 + (threadIdx.x >> 5);
    int lane = threadIdx.x & 31;
    const float* xr = x + (size_t)row * Cdim;
    float v[6]; float s = 0.f, ss = 0.f;
#pragma unroll
    for (int i = 0; i < 6; i++) { v[i] = xr[lane + 32 * i]; s += v[i]; ss += v[i] * v[i]; }
#pragma unroll
    for (int o = 16; o > 0; o >>= 1) {
        s  += __shfl_xor_sync(0xffffffffu, s,  o);
        ss += __shfl_xor_sync(0xffffffffu, ss, o);
    }
    float mu   = s * (1.f / Cdim);
    float var  = ss * (1.f / Cdim) - mu * mu;
    float rstd = rsqrtf(var + LN_EPS);
    __nv_bfloat16* orow = out + (size_t)row * Cdim;
#pragma unroll
    for (int i = 0; i < 6; i++) {
        int c = lane + 32 * i;
        orow[c] = __float2bfloat16((v[i] - mu) * rstd * gamma[c] + beta[c]);
    }
}

// ---------------------------------------------------------------------------
// bf16 GEMM with cp.async double buffering (round-4 structure, 422us best).
// BM=128, BN=64, BK=32, 8 warps (4x2), warp tile 32x32 via m16n8k16.
// MODE 0: split (cols<192 -> Y1 none; >=192 -> Y2 silu), stride Cdim
// MODE 1: elu+1 -> Y1 (bf16, stride N)
// MODE 2: none + fp32 resid -> Yf (fp32, stride N)
// ---------------------------------------------------------------------------
template <int MODE>
__global__ __launch_bounds__(256) void gemm2(
    const __nv_bfloat16* __restrict__ A, const __nv_bfloat16* __restrict__ W,
    const float* __restrict__ bias1, const float* __restrict__ bias2,
    const float* __restrict__ resid,
    __nv_bfloat16* __restrict__ Y1, __nv_bfloat16* __restrict__ Y2,
    float* __restrict__ Yf, int M, int N, int K)
{
    constexpr int BM = 128, BN = 64, BK = 32;
    constexpr int ASTR = 40;   // bf16 elems per A smem row (80B, conflict-free)
    constexpr int BSTR = 72;   // bf16 elems per B smem row (144B)
    constexpr int ASTAGE = BM * ASTR;
    constexpr int BSTAGE = BK * BSTR;
    __shared__ __align__(16) __nv_bfloat16 As[2 * ASTAGE];
    __shared__ __align__(16) __nv_bfloat16 Bs[2 * BSTAGE];

    int tid  = threadIdx.x;
    int bm   = blockIdx.y * BM, bn = blockIdx.x * BN;
    int warp = tid >> 5, lane = tid & 31;
    int wm   = (warp & 3) * 32, wn = (warp >> 2) * 32;

    uint32_t as_base = smem_u32(As);
    uint32_t bs_base = smem_u32(Bs);

    float acc[2][4][4];
#pragma unroll
    for (int i = 0; i < 2; i++)
#pragma unroll
        for (int j = 0; j < 4; j++)
#pragma unroll
            for (int l = 0; l < 4; l++) acc[i][j][l] = 0.f;

    int a_row = wm + (lane & 7) + ((lane >> 3) & 1) * 8;
    int a_col = (lane >> 4) * 8;
    int b_k   = (lane & 7) + ((lane >> 3) & 1) * 8;
    int b_n   = wn + (lane >> 4) * 8;

    auto load_stage = [&](int stage, int kt) {
        uint32_t ab = as_base + stage * ASTAGE * 2;
#pragma unroll
        for (int i = 0; i < 2; i++) {
            int idx = i * 256 + tid;
            int r = idx >> 2, c = idx & 3;
            cpa16(ab + (r * ASTR + c * 8) * 2,
                  A + (size_t)(bm + r) * K + kt * BK + c * 8);
        }
        uint32_t bb = bs_base + stage * BSTAGE * 2;
        {
            int r = tid >> 3, c = tid & 7;
            cpa16(bb + (r * BSTR + c * 8) * 2,
                  W + (size_t)(kt * BK + r) * N + bn + c * 8);
        }
        asm volatile("cp.async.commit_group;" ::: "memory");
    };

    const int KT = K / BK;
    load_stage(0, 0);
    for (int kt = 0; kt < KT; kt++) {
        if (kt + 1 < KT) {
            load_stage((kt + 1) & 1, kt + 1);
            asm volatile("cp.async.wait_group 1;" ::: "memory");
        } else {
            asm volatile("cp.async.wait_group 0;" ::: "memory");
        }
        __syncthreads();
        uint32_t ab = as_base + (kt & 1) * ASTAGE * 2;
        uint32_t bb = bs_base + (kt & 1) * BSTAGE * 2;
#pragma unroll
        for (int ks = 0; ks < 2; ks++) {
            uint32_t afr[2][4];
#pragma unroll
            for (int mt = 0; mt < 2; mt++) {
                uint32_t addr = ab + ((a_row + mt * 16) * ASTR + (a_col + ks * 16)) * 2;
                ldm_x4(afr[mt][0], afr[mt][1], afr[mt][2], afr[mt][3], addr);
            }
            uint32_t bfr[4][2];
#pragma unroll
            for (int p = 0; p < 2; p++) {
                uint32_t addr = bb + ((b_k + ks * 16) * BSTR + (b_n + p * 16)) * 2;
                uint32_t r0, r1, r2, r3;
                ldm_x4t(r0, r1, r2, r3, addr);
                bfr[p * 2 + 0][0] = r0; bfr[p * 2 + 0][1] = r1;
                bfr[p * 2 + 1][0] = r2; bfr[p * 2 + 1][1] = r3;
            }
#pragma unroll
            for (int mt = 0; mt < 2; mt++)
#pragma unroll
                for (int nt = 0; nt < 4; nt++)
                    mma16816(acc[mt][nt], afr[mt][0], afr[mt][1], afr[mt][2],
                             afr[mt][3], bfr[nt][0], bfr[nt][1]);
        }
        __syncthreads();
    }

    // epilogue (fast-math activations)
    int r0 = lane >> 2, c0 = (lane & 3) * 2;
    bool first = (bn < Cdim);
#pragma unroll
    for (int mt = 0; mt < 2; mt++) {
#pragma unroll
        for (int half = 0; half < 2; half++) {
            int row = bm + wm + mt * 16 + r0 + half * 8;
#pragma unroll
            for (int nt = 0; nt < 4; nt++) {
                int col = bn + wn + nt * 8 + c0;
                float v0 = acc[mt][nt][half * 2 + 0];
                float v1 = acc[mt][nt][half * 2 + 1];
                if (MODE == 0) {
                    int cl = first ? col : col - Cdim;
                    const float* bs = first ? bias1 : bias2;
                    v0 += bs[cl]; v1 += bs[cl + 1];
                    if (!first) { v0 = fast_silu(v0); v1 = fast_silu(v1); }
                    __nv_bfloat16* dst = first ? Y1 : Y2;
                    *(__nv_bfloat162*)&dst[(size_t)row * Cdim + cl] = pack2(v0, v1);
                } else if (MODE == 1) {
                    v0 += bias1[col]; v1 += bias1[col + 1];
                    v0 = fast_elu1(v0); v1 = fast_elu1(v1);
                    *(__nv_bfloat162*)&Y1[(size_t)row * N + col] = pack2(v0, v1);
                } else {
                    v0 += bias1[col]; v1 += bias1[col + 1];
                    float2 rr = *(const float2*)&resid[(size_t)row * N + col];
                    v0 += rr.x; v1 += rr.y;
                    float2 o; o.x = v0; o.y = v1;
                    *(float2*)&Yf[(size_t)row * N + col] = o;
                }
            }
        }
    }
}

// ---------------------------------------------------------------------------
// Depthwise 3x3 SAME conv + silu, bf16x2: 96 threads (2ch each), 4 rows/thread
// ---------------------------------------------------------------------------
__global__ void dwconv_silu_kernel(const __nv_bfloat162* __restrict__ in,
                                   const float* __restrict__ w,
                                   const float* __restrict__ bias,
                                   __nv_bfloat162* __restrict__ out)
{
    int blk = blockIdx.x;
    int c2  = threadIdx.x;              // 0..95
    int x   = blk % Wimg;
    int t   = blk / Wimg;
    int y4  = t % (Himg / 4);
    int b   = t / (Himg / 4);
    int y0  = y4 * 4;

    float2 wv[9];
#pragma unroll
    for (int i = 0; i < 9; i++) wv[i] = *(const float2*)&w[i * Cdim + 2 * c2];
    float2 bb = *(const float2*)&bias[2 * c2];
    float2 acc[4];
#pragma unroll
    for (int i = 0; i < 4; i++) acc[i] = bb;

#pragma unroll
    for (int dx = 0; dx < 3; dx++) {
        int xx = x + dx - 1;
        if (xx < 0 || xx >= Wimg) continue;
#pragma unroll
        for (int ry = -1; ry < 5; ry++) {
            int yy = y0 + ry;
            if (yy < 0 || yy >= Himg) continue;
            float2 v = __bfloat1622float2(in[((size_t)(b * Himg + yy) * Wimg + xx) * 96 + c2]);
#pragma unroll
            for (int oy = 0; oy < 4; oy++) {
                int dy = ry - oy + 1;
                if (dy >= 0 && dy < 3) {
                    acc[oy].x = fmaf(v.x, wv[dy * 3 + dx].x, acc[oy].x);
                    acc[oy].y = fmaf(v.y, wv[dy * 3 + dx].y, acc[oy].y);
                }
            }
        }
    }
#pragma unroll
    for (int oy = 0; oy < 4; oy++) {
        out[((size_t)(b * Himg + y0 + oy) * Wimg + x) * 96 + c2] =
            pack2(fast_silu(acc[oy].x), fast_silu(acc[oy].y));
    }
}

// Fused: g = (att + dwconv(h)+lepe_b) * act_res
__global__ void lepe_mul_kernel(const __nv_bfloat162* __restrict__ hin,
                                const float* __restrict__ w,
                                const float* __restrict__ bias,
                                const float* __restrict__ att,
                                const __nv_bfloat162* __restrict__ actres,
                                __nv_bfloat162* __restrict__ out)
{
    int blk = blockIdx.x;
    int c2  = threadIdx.x;
    int x   = blk % Wimg;
    int t   = blk / Wimg;
    int y4  = t % (Himg / 4);
    int b   = t / (Himg / 4);
    int y0  = y4 * 4;

    float2 wv[9];
#pragma unroll
    for (int i = 0; i < 9; i++) wv[i] = *(const float2*)&w[i * Cdim + 2 * c2];
    float2 bb = *(const float2*)&bias[2 * c2];
    float2 acc[4];
#pragma unroll
    for (int i = 0; i < 4; i++) acc[i] = bb;

#pragma unroll
    for (int dx = 0; dx < 3; dx++) {
        int xx = x + dx - 1;
        if (xx < 0 || xx >= Wimg) continue;
#pragma unroll
        for (int ry = -1; ry < 5; ry++) {
            int yy = y0 + ry;
            if (yy < 0 || yy >= Himg) continue;
            float2 v = __bfloat1622float2(hin[((size_t)(b * Himg + yy) * Wimg + xx) * 96 + c2]);
#pragma unroll
            for (int oy = 0; oy < 4; oy++) {
                int dy = ry - oy + 1;
                if (dy >= 0 && dy < 3) {
                    acc[oy].x = fmaf(v.x, wv[dy * 3 + dx].x, acc[oy].x);
                    acc[oy].y = fmaf(v.y, wv[dy * 3 + dx].y, acc[oy].y);
                }
            }
        }
    }
#pragma unroll
    for (int oy = 0; oy < 4; oy++) {
        size_t pix = (size_t)(b * Himg + y0 + oy) * Wimg + x;
        float2 at = *(const float2*)&att[pix * Cdim + 2 * c2];
        float2 ar = __bfloat1622float2(actres[pix * 96 + c2]);
        out[pix * 96 + c2] = pack2((at.x + acc[oy].x) * ar.x,
                                   (at.y + acc[oy].y) * ar.y);
    }
}

// ---------------------------------------------------------------------------
// kv[b,h] = k^T v / L  (32x32), kmean = mean_n k
// ---------------------------------------------------------------------------
__global__ void kv_kernel(const __nv_bfloat16* __restrict__ qk,
                          const __nv_bfloat16* __restrict__ hv,
                          float* __restrict__ kv, float* __restrict__ km)
{
    int bh = blockIdx.x;
    int b = bh / NHEAD, hd = bh % NHEAD;
    __shared__ float skv[HDIM * HDIM];
    __shared__ float skm[HDIM];
    int tid = threadIdx.x;
    for (int i = tid; i < HDIM * HDIM; i += blockDim.x) skv[i] = 0.f;
    if (tid < HDIM) skm[tid] = 0.f;
    __syncthreads();

    int lane = tid & 31, warp = tid >> 5;
    float acc[HDIM];
#pragma unroll
    for (int e = 0; e < HDIM; e++) acc[e] = 0.f;
    float acck = 0.f;

    for (int n = warp; n < Lseq; n += 8) {
        size_t rowq = (size_t)(b * Lseq + n) * (2 * Cdim);
        float kd = __bfloat162float(qk[rowq + Cdim + hd * HDIM + lane]);
        float ve = __bfloat162float(hv[(size_t)(b * Lseq + n) * Cdim + hd * HDIM + lane]);
        acck += kd;
#pragma unroll
        for (int e = 0; e < HDIM; e++)
            acc[e] = fmaf(kd, __shfl_sync(0xffffffffu, ve, e), acc[e]);
    }
#pragma unroll
    for (int e = 0; e < HDIM; e++) atomicAdd(&skv[lane * HDIM + e], acc[e]);
    atomicAdd(&skm[lane], acck);
    __syncthreads();

    const float invL = 1.f / (float)Lseq;
    for (int i = tid; i < HDIM * HDIM; i += blockDim.x)
        kv[(size_t)bh * HDIM * HDIM + i] = skv[i] * invL;
    if (tid < HDIM) km[bh * HDIM + tid] = skm[tid] * invL;
}

// ---------------------------------------------------------------------------
// att[n, h*32+e] = z * sum_d q[n,d]*kv[d,e];  z = 1/(q.kmean + 1e-6)
// ---------------------------------------------------------------------------
__global__ void att_kernel(const __nv_bfloat16* __restrict__ qk,
                           const float* __restrict__ kv,
                           const float* __restrict__ km, float* __restrict__ att)
{
    int bh = blockIdx.x;
    int b = bh / NHEAD, hd = bh % NHEAD;
    __shared__ float skv[HDIM * HDIM];
    __shared__ float skm[HDIM];
    int tid = threadIdx.x;
    for (int i = tid; i < HDIM * HDIM; i += blockDim.x)
        skv[i] = kv[(size_t)bh * HDIM * HDIM + i];
    if (tid < HDIM) skm[tid] = km[bh * HDIM + tid];
    __syncthreads();

    int lane = tid & 31, warp = tid >> 5;
    const int per = Lseq / 8;
    int n0 = blockIdx.y * per;
    for (int n = n0 + warp; n < n0 + per; n += 8) {
        float qe = __bfloat162float(qk[(size_t)(b * Lseq + n) * (2 * Cdim) + hd * HDIM + lane]);
        float p = qe * skm[lane];
#pragma unroll
        for (int o = 16; o > 0; o >>= 1) p += __shfl_xor_sync(0xffffffffu, p, o);
        float z = __fdividef(1.f, p + 1e-6f);
        float a = 0.f;
#pragma unroll
        for (int d = 0; d < HDIM; d++)
            a = fmaf(__shfl_sync(0xffffffffu, qe, d), skv[d * HDIM + lane], a);
        att[(size_t)(b * Lseq + n) * Cdim + hd * HDIM + lane] = a * z;
    }
}

// ---------------------------------------------------------------------------
extern "C" void kernel_launch(void* const* d_in, const int* in_sizes, int n_in,
                              void* d_out, int out_size)
{
    const float* x      = (const float*)d_in[0];
    const float* norm_g = (const float*)d_in[1];
    const float* norm_b = (const float*)d_in[2];
    const float* in_w   = (const float*)d_in[3];
    const float* in_b   = (const float*)d_in[4];
    const float* act_w  = (const float*)d_in[5];
    const float* act_b  = (const float*)d_in[6];
    const float* dwc_w  = (const float*)d_in[7];
    const float* dwc_b  = (const float*)d_in[8];
    const float* qk_w   = (const float*)d_in[9];
    const float* qk_b   = (const float*)d_in[10];
    const float* lepe_w = (const float*)d_in[11];
    const float* lepe_b = (const float*)d_in[12];
    const float* out_w  = (const float*)d_in[13];
    const float* out_b  = (const float*)d_in[14];
    float* out = (float*)d_out;

    __nv_bfloat16 *xnb, *h0b, *actb, *hb, *qkb, *gb;
    float *att, *kv, *km;
    __nv_bfloat16 *wcat, *qkw, *outw;
    cudaGetSymbolAddress((void**)&xnb,  g_xnb);
    cudaGetSymbolAddress((void**)&h0b,  g_h0b);
    cudaGetSymbolAddress((void**)&actb, g_actb);
    cudaGetSymbolAddress((void**)&hb,   g_hb);
    cudaGetSymbolAddress((void**)&qkb,  g_qkb);
    cudaGetSymbolAddress((void**)&gb,   g_gb);
    cudaGetSymbolAddress((void**)&att,  g_att);
    cudaGetSymbolAddress((void**)&kv,   g_kv);
    cudaGetSymbolAddress((void**)&km,   g_km);
    cudaGetSymbolAddress((void**)&wcat, g_wcat);
    cudaGetSymbolAddress((void**)&qkw,  g_qkw);
    cudaGetSymbolAddress((void**)&outw, g_outw);

    // 0) convert weights to bf16 (+ concat in_w|act_w)
    convw_kernel<<<(Cdim * 2 * Cdim + 255) / 256, 256>>>(in_w, act_w, qk_w, out_w);

    // 1) LayerNorm -> bf16
    ln_kernel<<<BL / 8, 256>>>(x, norm_g, norm_b, xnb);

    // 2) fused in-proj + act-proj GEMM (N=384, split epilogue)
    gemm2<0><<<dim3(6, BL / 128), 256>>>(xnb, wcat, in_b, act_b, nullptr,
                                         h0b, actb, nullptr, BL, 2 * Cdim, Cdim);

    // 3) dwconv + silu -> h
    int dwgrid = BATCH * (Himg / 4) * Wimg;
    dwconv_silu_kernel<<<dwgrid, 96>>>((const __nv_bfloat162*)h0b, dwc_w, dwc_b,
                                       (__nv_bfloat162*)hb);

    // 4) qk-proj with elu+1
    gemm2<1><<<dim3(6, BL / 128), 256>>>(hb, qkw, qk_b, nullptr, nullptr,
                                         qkb, nullptr, nullptr, BL, 2 * Cdim, Cdim);

    // 5) linear attention
    kv_kernel<<<BATCH * NHEAD, 256>>>(qkb, hb, kv, km);
    att_kernel<<<dim3(BATCH * NHEAD, 8), 256>>>(qkb, kv, km, att);

    // 6) g = (att + lepe) * act_res -> gb
    lepe_mul_kernel<<<dwgrid, 96>>>((const __nv_bfloat162*)hb, lepe_w, lepe_b, att,
                                    (const __nv_bfloat162*)actb, (__nv_bfloat162*)gb);

    // 7) out-proj + bias + shortcut -> fp32 out
    gemm2<2><<<dim3(3, BL / 128), 256>>>(gb, outw, out_b, nullptr, x,
                                         nullptr, nullptr, out, BL, Cdim, Cdim);
}

// round 9
// speedup vs baseline: 1.3994x; 1.0079x over previous
#include <cuda_runtime.h>
#include <cuda_bf16.h>
#include <stdint.h>
#include <math.h>

// ---------------------------------------------------------------------------
// EMLLA block: weight-resident persistent-CTA bf16 HMMA GEMMs.
// Each GEMM CTA keeps a 192-col slice of W in smem (76.8KB) for its whole
// lifetime and streams M-tiles of A (double-buffered cp.async), cutting
// LDGSTS volume ~3.3x vs round 4/8 (the measured bottleneck).
// B=16, H=W=56, C=192, 6 heads x 32.
// ---------------------------------------------------------------------------

constexpr int Himg = 56, Wimg = 56, Lseq = 3136, Cdim = 192;
constexpr int NHEAD = 6, HDIM = 32, BATCH = 16;
constexpr int BL = BATCH * Lseq;              // 50176 rows
constexpr float LN_EPS = 1e-5f;
constexpr int GK = 192;                       // all GEMM K

// Scratch (device globals: allocation-free, graph-capture safe)
__device__ __align__(16) __nv_bfloat16 g_xnb [(size_t)BL * Cdim];
__device__ __align__(16) __nv_bfloat16 g_h0b [(size_t)BL * Cdim];
__device__ __align__(16) __nv_bfloat16 g_actb[(size_t)BL * Cdim];
__device__ __align__(16) __nv_bfloat16 g_hb  [(size_t)BL * Cdim];
__device__ __align__(16) __nv_bfloat16 g_qkb [(size_t)BL * 2 * Cdim];
__device__ __align__(16) __nv_bfloat16 g_gb  [(size_t)BL * Cdim];
__device__ __align__(16) float g_att[(size_t)BL * Cdim];
__device__ __align__(16) float g_kv [BATCH * NHEAD * HDIM * HDIM];
__device__ __align__(16) float g_km [BATCH * NHEAD * HDIM];
// bf16 weights, [K, N] layout
__device__ __align__(16) __nv_bfloat16 g_wcat[Cdim * 2 * Cdim];   // in_w | act_w
__device__ __align__(16) __nv_bfloat16 g_qkw [Cdim * 2 * Cdim];
__device__ __align__(16) __nv_bfloat16 g_outw[Cdim * Cdim];

// ---------------------------------------------------------------------------
// helpers
// ---------------------------------------------------------------------------
__device__ __forceinline__ uint32_t smem_u32(const void* p) {
    return (uint32_t)__cvta_generic_to_shared(p);
}
__device__ __forceinline__ void ldm_x4(uint32_t& r0, uint32_t& r1, uint32_t& r2,
                                       uint32_t& r3, uint32_t a) {
    asm volatile("ldmatrix.sync.aligned.m8n8.x4.shared.b16 {%0,%1,%2,%3}, [%4];"
                 : "=r"(r0), "=r"(r1), "=r"(r2), "=r"(r3) : "r"(a));
}
__device__ __forceinline__ void ldm_x4t(uint32_t& r0, uint32_t& r1, uint32_t& r2,
                                        uint32_t& r3, uint32_t a) {
    asm volatile("ldmatrix.sync.aligned.m8n8.x4.trans.shared.b16 {%0,%1,%2,%3}, [%4];"
                 : "=r"(r0), "=r"(r1), "=r"(r2), "=r"(r3) : "r"(a));
}
__device__ __forceinline__ void mma16816(float* c, uint32_t a0, uint32_t a1,
                                         uint32_t a2, uint32_t a3,
                                         uint32_t b0, uint32_t b1) {
    asm volatile(
        "mma.sync.aligned.m16n8k16.row.col.f32.bf16.bf16.f32 "
        "{%0,%1,%2,%3}, {%4,%5,%6,%7}, {%8,%9}, {%0,%1,%2,%3};"
        : "+f"(c[0]), "+f"(c[1]), "+f"(c[2]), "+f"(c[3])
        : "r"(a0), "r"(a1), "r"(a2), "r"(a3), "r"(b0), "r"(b1));
}
__device__ __forceinline__ void cpa16(uint32_t dst, const void* src) {
    asm volatile("cp.async.cg.shared.global [%0], [%1], 16;" :: "r"(dst), "l"(src));
}
__device__ __forceinline__ void cpa_commit() {
    asm volatile("cp.async.commit_group;" ::: "memory");
}
__device__ __forceinline__ void cpa_wait1() {
    asm volatile("cp.async.wait_group 1;" ::: "memory");
}
__device__ __forceinline__ void cpa_wait0() {
    asm volatile("cp.async.wait_group 0;" ::: "memory");
}
__device__ __forceinline__ __nv_bfloat162 pack2(float a, float b) {
    return __floats2bfloat162_rn(a, b);
}
__device__ __forceinline__ float fast_silu(float v) {
    return __fdividef(v, 1.f + __expf(-v));
}
__device__ __forceinline__ float fast_elu1(float v) {
    return (v > 0.f) ? v + 1.f : __expf(v);
}

// ---------------------------------------------------------------------------
// weight conversion: fp32 [K,N] -> bf16 [K,N] (+ concat in_w|act_w)
// ---------------------------------------------------------------------------
__global__ void convw_kernel(const float* __restrict__ in_w, const float* __restrict__ act_w,
                             const float* __restrict__ qk_w, const float* __restrict__ out_w)
{
    int i = blockIdx.x * 256 + threadIdx.x;
    if (i < Cdim * 2 * Cdim) {
        int r = i / (2 * Cdim), c = i % (2 * Cdim);
        float v = (c < Cdim) ? in_w[r * Cdim + c] : act_w[r * Cdim + (c - Cdim)];
        g_wcat[i] = __float2bfloat16(v);
        g_qkw[i]  = __float2bfloat16(qk_w[i]);
    }
    if (i < Cdim * Cdim) g_outw[i] = __float2bfloat16(out_w[i]);
}

// ---------------------------------------------------------------------------
// LayerNorm -> bf16: one warp per row of 192
// ---------------------------------------------------------------------------
__global__ void ln_kernel(const float* __restrict__ x, const float* __restrict__ gamma,
                          const float* __restrict__ beta, __nv_bfloat16* __restrict__ out) {
    int row  = blockIdx.x * 8 + (threadIdx.x >> 5);
    int lane = threadIdx.x & 31;
    const float* xr = x + (size_t)row * Cdim;
    float v[6]; float s = 0.f, ss = 0.f;
#pragma unroll
    for (int i = 0; i < 6; i++) { v[i] = xr[lane + 32 * i]; s += v[i]; ss += v[i] * v[i]; }
#pragma unroll
    for (int o = 16; o > 0; o >>= 1) {
        s  += __shfl_xor_sync(0xffffffffu, s,  o);
        ss += __shfl_xor_sync(0xffffffffu, ss, o);
    }
    float mu   = s * (1.f / Cdim);
    float var  = ss * (1.f / Cdim) - mu * mu;
    float rstd = rsqrtf(var + LN_EPS);
    __nv_bfloat16* orow = out + (size_t)row * Cdim;
#pragma unroll
    for (int i = 0; i < 6; i++) {
        int c = lane + 32 * i;
        orow[c] = __float2bfloat16((v[i] - mu) * rstd * gamma[c] + beta[c]);
    }
}

// ---------------------------------------------------------------------------
// Persistent weight-resident bf16 GEMM.
// B slice [192 K x 192 N] resident in smem (BSTR=200 elems -> 400B rows,
// 400 % 128 = 16 -> conflict-free ldmatrix). A tiles 128x32 double-buffered
// (ASTR=40 -> 80B rows, verified conflict-free). 8 warps: 4(M) x 2(N),
// warp tile 32x96 via m16n8k16. Each CTA loops M-tiles with stride gridDim.y.
// MODE 0: group0 -> Y1 none, group1 -> Y2 silu (both stride Cdim)
// MODE 1: elu+1 -> Y1 (stride N)
// MODE 2: +fp32 resid -> Yf (stride N)
// ---------------------------------------------------------------------------
constexpr int ASTR = 40, BSTR = 200;
constexpr int ASTAGE_B = 128 * ASTR * 2;          // 10240 bytes per stage
constexpr int BRES_B   = GK * BSTR * 2;           // 76800 bytes
constexpr int SMEMP    = BRES_B + 2 * ASTAGE_B;   // 97280 bytes

template <int MODE>
__global__ __launch_bounds__(256, 1) void gemm_pers(
    const __nv_bfloat16* __restrict__ A, const __nv_bfloat16* __restrict__ W,
    const float* __restrict__ bias1, const float* __restrict__ bias2,
    const float* __restrict__ resid,
    __nv_bfloat16* __restrict__ Y1, __nv_bfloat16* __restrict__ Y2,
    float* __restrict__ Yf, int N, int mtiles)
{
    extern __shared__ __align__(16) char smem[];
    uint32_t bs_base = smem_u32(smem);
    uint32_t as_base = bs_base + BRES_B;

    int tid  = threadIdx.x;
    int bn   = blockIdx.x * 192;
    int warp = tid >> 5, lane = tid & 31;
    int wm   = (warp & 3) * 32, wn = (warp >> 2) * 96;

    // ---- load resident B slice: 192 rows x 24 chunks ----
#pragma unroll
    for (int i = 0; i < 18; i++) {
        int idx = i * 256 + tid;                  // 4608 chunks
        int r = idx / 24, c = idx % 24;
        cpa16(bs_base + (r * BSTR + c * 8) * 2, W + (size_t)r * N + bn + c * 8);
    }
    cpa_commit();

    auto load_a = [&](int stage, int bm, int kt) {
        uint32_t ab = as_base + stage * ASTAGE_B;
#pragma unroll
        for (int i = 0; i < 2; i++) {
            int idx = i * 256 + tid;              // 512 chunks
            int r = idx >> 2, c = idx & 3;
            cpa16(ab + (r * ASTR + c * 8) * 2,
                  A + (size_t)(bm + r) * GK + kt * 32 + c * 8);
        }
        cpa_commit();
    };

    // fragment addresses
    int a_row = wm + (lane & 7) + ((lane >> 3) & 1) * 8;
    int a_col = (lane >> 4) * 8;
    int b_k   = (lane & 7) + ((lane >> 3) & 1) * 8;
    int b_n   = wn + (lane >> 4) * 8;
    int r0 = lane >> 2, c0 = (lane & 3) * 2;
    bool first = (blockIdx.x == 0);

    // preload bias (fixed per thread)
    float bv[12][2];
    {
        const float* bsrc = (MODE == 0) ? (first ? bias1 : bias2) : bias1;
#pragma unroll
        for (int nt = 0; nt < 12; nt++) {
            int cl = wn + nt * 8 + c0;            // local col in 0..191
            int bi = (MODE == 0) ? cl : bn + cl;
            bv[nt][0] = bsrc[bi];
            bv[nt][1] = bsrc[bi + 1];
        }
    }

    int mt = blockIdx.y;
    if (mt < mtiles) load_a(0, mt * 128, 0);

    for (; mt < mtiles; mt += gridDim.y) {
        int bm = mt * 128;
        int next_mt = mt + gridDim.y;

        float acc[2][12][4];
#pragma unroll
        for (int i = 0; i < 2; i++)
#pragma unroll
            for (int j = 0; j < 12; j++)
#pragma unroll
                for (int l = 0; l < 4; l++) acc[i][j][l] = 0.f;

#pragma unroll
        for (int kt = 0; kt < 6; kt++) {
            bool has_next = (kt < 5) || (next_mt < mtiles);
            if (has_next) {
                if (kt < 5) load_a((kt + 1) & 1, bm, kt + 1);
                else        load_a(0, next_mt * 128, 0);
                cpa_wait1();
            } else {
                cpa_wait0();
            }
            __syncthreads();
            uint32_t ab = as_base + (kt & 1) * ASTAGE_B;
#pragma unroll
            for (int ks = 0; ks < 2; ks++) {
                uint32_t afr[2][4];
#pragma unroll
                for (int mti = 0; mti < 2; mti++) {
                    uint32_t addr = ab + ((a_row + mti * 16) * ASTR + a_col + ks * 16) * 2;
                    ldm_x4(afr[mti][0], afr[mti][1], afr[mti][2], afr[mti][3], addr);
                }
                uint32_t bfr[12][2];
#pragma unroll
                for (int p = 0; p < 6; p++) {
                    uint32_t addr = bs_base +
                        ((kt * 32 + ks * 16 + b_k) * BSTR + b_n + p * 16) * 2;
                    uint32_t t0, t1, t2, t3;
                    ldm_x4t(t0, t1, t2, t3, addr);
                    bfr[p * 2 + 0][0] = t0; bfr[p * 2 + 0][1] = t1;
                    bfr[p * 2 + 1][0] = t2; bfr[p * 2 + 1][1] = t3;
                }
#pragma unroll
                for (int mti = 0; mti < 2; mti++)
#pragma unroll
                    for (int nt = 0; nt < 12; nt++)
                        mma16816(acc[mti][nt], afr[mti][0], afr[mti][1],
                                 afr[mti][2], afr[mti][3], bfr[nt][0], bfr[nt][1]);
            }
            __syncthreads();
        }

        // ---- epilogue ----
#pragma unroll
        for (int mti = 0; mti < 2; mti++) {
#pragma unroll
            for (int half = 0; half < 2; half++) {
                int row = bm + wm + mti * 16 + r0 + half * 8;
#pragma unroll
                for (int nt = 0; nt < 12; nt++) {
                    int cl = wn + nt * 8 + c0;    // local col
                    float v0 = acc[mti][nt][half * 2 + 0] + bv[nt][0];
                    float v1 = acc[mti][nt][half * 2 + 1] + bv[nt][1];
                    if (MODE == 0) {
                        if (!first) { v0 = fast_silu(v0); v1 = fast_silu(v1); }
                        __nv_bfloat16* dst = first ? Y1 : Y2;
                        *(__nv_bfloat162*)&dst[(size_t)row * Cdim + cl] = pack2(v0, v1);
                    } else if (MODE == 1) {
                        v0 = fast_elu1(v0); v1 = fast_elu1(v1);
                        *(__nv_bfloat162*)&Y1[(size_t)row * N + bn + cl] = pack2(v0, v1);
                    } else {
                        float2 rr = *(const float2*)&resid[(size_t)row * N + bn + cl];
                        float2 o; o.x = v0 + rr.x; o.y = v1 + rr.y;
                        *(float2*)&Yf[(size_t)row * N + bn + cl] = o;
                    }
                }
            }
        }
    }
}

// ---------------------------------------------------------------------------
// Depthwise 3x3 SAME conv + silu, bf16x2: 96 threads (2ch each), 4 rows/thread
// ---------------------------------------------------------------------------
__global__ void dwconv_silu_kernel(const __nv_bfloat162* __restrict__ in,
                                   const float* __restrict__ w,
                                   const float* __restrict__ bias,
                                   __nv_bfloat162* __restrict__ out)
{
    int blk = blockIdx.x;
    int c2  = threadIdx.x;              // 0..95
    int x   = blk % Wimg;
    int t   = blk / Wimg;
    int y4  = t % (Himg / 4);
    int b   = t / (Himg / 4);
    int y0  = y4 * 4;

    float2 wv[9];
#pragma unroll
    for (int i = 0; i < 9; i++) wv[i] = *(const float2*)&w[i * Cdim + 2 * c2];
    float2 bb = *(const float2*)&bias[2 * c2];
    float2 acc[4];
#pragma unroll
    for (int i = 0; i < 4; i++) acc[i] = bb;

#pragma unroll
    for (int dx = 0; dx < 3; dx++) {
        int xx = x + dx - 1;
        if (xx < 0 || xx >= Wimg) continue;
#pragma unroll
        for (int ry = -1; ry < 5; ry++) {
            int yy = y0 + ry;
            if (yy < 0 || yy >= Himg) continue;
            float2 v = __bfloat1622float2(in[((size_t)(b * Himg + yy) * Wimg + xx) * 96 + c2]);
#pragma unroll
            for (int oy = 0; oy < 4; oy++) {
                int dy = ry - oy + 1;
                if (dy >= 0 && dy < 3) {
                    acc[oy].x = fmaf(v.x, wv[dy * 3 + dx].x, acc[oy].x);
                    acc[oy].y = fmaf(v.y, wv[dy * 3 + dx].y, acc[oy].y);
                }
            }
        }
    }
#pragma unroll
    for (int oy = 0; oy < 4; oy++) {
        out[((size_t)(b * Himg + y0 + oy) * Wimg + x) * 96 + c2] =
            pack2(fast_silu(acc[oy].x), fast_silu(acc[oy].y));
    }
}

// Fused: g = (att + dwconv(h)+lepe_b) * act_res
__global__ void lepe_mul_kernel(const __nv_bfloat162* __restrict__ hin,
                                const float* __restrict__ w,
                                const float* __restrict__ bias,
                                const float* __restrict__ att,
                                const __nv_bfloat162* __restrict__ actres,
                                __nv_bfloat162* __restrict__ out)
{
    int blk = blockIdx.x;
    int c2  = threadIdx.x;
    int x   = blk % Wimg;
    int t   = blk / Wimg;
    int y4  = t % (Himg / 4);
    int b   = t / (Himg / 4);
    int y0  = y4 * 4;

    float2 wv[9];
#pragma unroll
    for (int i = 0; i < 9; i++) wv[i] = *(const float2*)&w[i * Cdim + 2 * c2];
    float2 bb = *(const float2*)&bias[2 * c2];
    float2 acc[4];
#pragma unroll
    for (int i = 0; i < 4; i++) acc[i] = bb;

#pragma unroll
    for (int dx = 0; dx < 3; dx++) {
        int xx = x + dx - 1;
        if (xx < 0 || xx >= Wimg) continue;
#pragma unroll
        for (int ry = -1; ry < 5; ry++) {
            int yy = y0 + ry;
            if (yy < 0 || yy >= Himg) continue;
            float2 v = __bfloat1622float2(hin[((size_t)(b * Himg + yy) * Wimg + xx) * 96 + c2]);
#pragma unroll
            for (int oy = 0; oy < 4; oy++) {
                int dy = ry - oy + 1;
                if (dy >= 0 && dy < 3) {
                    acc[oy].x = fmaf(v.x, wv[dy * 3 + dx].x, acc[oy].x);
                    acc[oy].y = fmaf(v.y, wv[dy * 3 + dx].y, acc[oy].y);
                }
            }
        }
    }
#pragma unroll
    for (int oy = 0; oy < 4; oy++) {
        size_t pix = (size_t)(b * Himg + y0 + oy) * Wimg + x;
        float2 at = *(const float2*)&att[pix * Cdim + 2 * c2];
        float2 ar = __bfloat1622float2(actres[pix * 96 + c2]);
        out[pix * 96 + c2] = pack2((at.x + acc[oy].x) * ar.x,
                                   (at.y + acc[oy].y) * ar.y);
    }
}

// ---------------------------------------------------------------------------
// kv[b,h] = k^T v / L  (32x32), kmean = mean_n k
// ---------------------------------------------------------------------------
__global__ void kv_kernel(const __nv_bfloat16* __restrict__ qk,
                          const __nv_bfloat16* __restrict__ hv,
                          float* __restrict__ kv, float* __restrict__ km)
{
    int bh = blockIdx.x;
    int b = bh / NHEAD, hd = bh % NHEAD;
    __shared__ float skv[HDIM * HDIM];
    __shared__ float skm[HDIM];
    int tid = threadIdx.x;
    for (int i = tid; i < HDIM * HDIM; i += blockDim.x) skv[i] = 0.f;
    if (tid < HDIM) skm[tid] = 0.f;
    __syncthreads();

    int lane = tid & 31, warp = tid >> 5;
    float acc[HDIM];
#pragma unroll
    for (int e = 0; e < HDIM; e++) acc[e] = 0.f;
    float acck = 0.f;

    for (int n = warp; n < Lseq; n += 8) {
        size_t rowq = (size_t)(b * Lseq + n) * (2 * Cdim);
        float kd = __bfloat162float(qk[rowq + Cdim + hd * HDIM + lane]);
        float ve = __bfloat162float(hv[(size_t)(b * Lseq + n) * Cdim + hd * HDIM + lane]);
        acck += kd;
#pragma unroll
        for (int e = 0; e < HDIM; e++)
            acc[e] = fmaf(kd, __shfl_sync(0xffffffffu, ve, e), acc[e]);
    }
#pragma unroll
    for (int e = 0; e < HDIM; e++) atomicAdd(&skv[lane * HDIM + e], acc[e]);
    atomicAdd(&skm[lane], acck);
    __syncthreads();

    const float invL = 1.f / (float)Lseq;
    for (int i = tid; i < HDIM * HDIM; i += blockDim.x)
        kv[(size_t)bh * HDIM * HDIM + i] = skv[i] * invL;
    if (tid < HDIM) km[bh * HDIM + tid] = skm[tid] * invL;
}

// ---------------------------------------------------------------------------
// att[n, h*32+e] = z * sum_d q[n,d]*kv[d,e];  z = 1/(q.kmean + 1e-6)
// ---------------------------------------------------------------------------
__global__ void att_kernel(const __nv_bfloat16* __restrict__ qk,
                           const float* __restrict__ kv,
                           const float* __restrict__ km, float* __restrict__ att)
{
    int bh = blockIdx.x;
    int b = bh / NHEAD, hd = bh % NHEAD;
    __shared__ float skv[HDIM * HDIM];
    __shared__ float skm[HDIM];
    int tid = threadIdx.x;
    for (int i = tid; i < HDIM * HDIM; i += blockDim.x)
        skv[i] = kv[(size_t)bh * HDIM * HDIM + i];
    if (tid < HDIM) skm[tid] = km[bh * HDIM + tid];
    __syncthreads();

    int lane = tid & 31, warp = tid >> 5;
    const int per = Lseq / 8;
    int n0 = blockIdx.y * per;
    for (int n = n0 + warp; n < n0 + per; n += 8) {
        float qe = __bfloat162float(qk[(size_t)(b * Lseq + n) * (2 * Cdim) + hd * HDIM + lane]);
        float p = qe * skm[lane];
#pragma unroll
        for (int o = 16; o > 0; o >>= 1) p += __shfl_xor_sync(0xffffffffu, p, o);
        float z = __fdividef(1.f, p + 1e-6f);
        float a = 0.f;
#pragma unroll
        for (int d = 0; d < HDIM; d++)
            a = fmaf(__shfl_sync(0xffffffffu, qe, d), skv[d * HDIM + lane], a);
        att[(size_t)(b * Lseq + n) * Cdim + hd * HDIM + lane] = a * z;
    }
}

// ---------------------------------------------------------------------------
extern "C" void kernel_launch(void* const* d_in, const int* in_sizes, int n_in,
                              void* d_out, int out_size)
{
    const float* x      = (const float*)d_in[0];
    const float* norm_g = (const float*)d_in[1];
    const float* norm_b = (const float*)d_in[2];
    const float* in_w   = (const float*)d_in[3];
    const float* in_b   = (const float*)d_in[4];
    const float* act_w  = (const float*)d_in[5];
    const float* act_b  = (const float*)d_in[6];
    const float* dwc_w  = (const float*)d_in[7];
    const float* dwc_b  = (const float*)d_in[8];
    const float* qk_w   = (const float*)d_in[9];
    const float* qk_b   = (const float*)d_in[10];
    const float* lepe_w = (const float*)d_in[11];
    const float* lepe_b = (const float*)d_in[12];
    const float* out_w  = (const float*)d_in[13];
    const float* out_b  = (const float*)d_in[14];
    float* out = (float*)d_out;

    __nv_bfloat16 *xnb, *h0b, *actb, *hb, *qkb, *gb, *wcat, *qkw, *outw;
    float *att, *kv, *km;
    cudaGetSymbolAddress((void**)&xnb,  g_xnb);
    cudaGetSymbolAddress((void**)&h0b,  g_h0b);
    cudaGetSymbolAddress((void**)&actb, g_actb);
    cudaGetSymbolAddress((void**)&hb,   g_hb);
    cudaGetSymbolAddress((void**)&qkb,  g_qkb);
    cudaGetSymbolAddress((void**)&gb,   g_gb);
    cudaGetSymbolAddress((void**)&att,  g_att);
    cudaGetSymbolAddress((void**)&kv,   g_kv);
    cudaGetSymbolAddress((void**)&km,   g_km);
    cudaGetSymbolAddress((void**)&wcat, g_wcat);
    cudaGetSymbolAddress((void**)&qkw,  g_qkw);
    cudaGetSymbolAddress((void**)&outw, g_outw);

    cudaFuncSetAttribute(gemm_pers<0>, cudaFuncAttributeMaxDynamicSharedMemorySize, SMEMP);
    cudaFuncSetAttribute(gemm_pers<1>, cudaFuncAttributeMaxDynamicSharedMemorySize, SMEMP);
    cudaFuncSetAttribute(gemm_pers<2>, cudaFuncAttributeMaxDynamicSharedMemorySize, SMEMP);

    // 0) weights -> bf16 (+ concat in_w|act_w)
    convw_kernel<<<(Cdim * 2 * Cdim + 255) / 256, 256>>>(in_w, act_w, qk_w, out_w);

    // 1) LayerNorm -> bf16
    ln_kernel<<<BL / 8, 256>>>(x, norm_g, norm_b, xnb);

    const int MT = BL / 128;   // 392 M-tiles

    // 2) fused in-proj + act-proj (N=384, 2 resident weight slices)
    gemm_pers<0><<<dim3(2, 74), 256, SMEMP>>>(
        xnb, wcat, in_b, act_b, nullptr, h0b, actb, nullptr, 2 * Cdim, MT);

    // 3) dwconv + silu -> h
    int dwgrid = BATCH * (Himg / 4) * Wimg;
    dwconv_silu_kernel<<<dwgrid, 96>>>((const __nv_bfloat162*)h0b, dwc_w, dwc_b,
                                       (__nv_bfloat162*)hb);

    // 4) qk-proj with elu+1 (N=384)
    gemm_pers<1><<<dim3(2, 74), 256, SMEMP>>>(
        hb, qkw, qk_b, nullptr, nullptr, qkb, nullptr, nullptr, 2 * Cdim, MT);

    // 5) linear attention
    kv_kernel<<<BATCH * NHEAD, 256>>>(qkb, hb, kv, km);
    att_kernel<<<dim3(BATCH * NHEAD, 8), 256>>>(qkb, kv, km, att);

    // 6) g = (att + lepe) * act_res -> gb
    lepe_mul_kernel<<<dwgrid, 96>>>((const __nv_bfloat162*)hb, lepe_w, lepe_b, att,
                                    (const __nv_bfloat162*)actb, (__nv_bfloat162*)gb);

    // 7) out-proj + bias + shortcut -> fp32 out (N=192, 1 slice)
    gemm_pers<2><<<dim3(1, 148), 256, SMEMP>>>(
        gb, outw, out_b, nullptr, x, nullptr, nullptr, out, Cdim, MT);
}